// round 1
// baseline (speedup 1.0000x reference)
#include <cuda_runtime.h>
#include <cuda_bf16.h>
#include <cstdint>
#include <math.h>

#define N_ROWS 16384
#define F_DIM  128
#define H1_DIM 64
#define H2_DIM 32
#define OUT_DIM 2
#define TILE   128
#define SSTRIDE 136   // 128 + 8 bf16 pad -> 272B row stride (16B aligned, conflict-free ldmatrix)

// ---------------- device scratch (no allocations allowed) ----------------
__device__ __nv_bfloat16 g_xn[N_ROWS * F_DIM];     // 4 MB normalized rows, bf16
__device__ float         g_neigh[N_ROWS * F_DIM];  // 8 MB neighbor sums
__device__ int           g_deg[N_ROWS];
__device__ float         g_logits[N_ROWS * OUT_DIM];
__device__ double        g_sum[2];
__device__ double        g_sq[2];

// ---------------- kernel 1: row norms, bf16 normalize, zero scratch ----------------
__global__ void __launch_bounds__(256) k_norm(const float* __restrict__ x) {
    if (blockIdx.x == 0 && threadIdx.x == 0) {
        g_sum[0] = 0.0; g_sum[1] = 0.0; g_sq[0] = 0.0; g_sq[1] = 0.0;
    }
    int warp = (blockIdx.x * blockDim.x + threadIdx.x) >> 5;
    int lane = threadIdx.x & 31;
    if (warp >= N_ROWS) return;
    const float* row = x + (size_t)warp * F_DIM;
    float v[4];
    float s = 0.f;
#pragma unroll
    for (int t = 0; t < 4; t++) { v[t] = row[lane + 32 * t]; s += v[t] * v[t]; }
#pragma unroll
    for (int o = 16; o > 0; o >>= 1) s += __shfl_xor_sync(0xffffffffu, s, o);
    float inv = 1.0f / (sqrtf(s) + 1e-12f);
#pragma unroll
    for (int t = 0; t < 4; t++) {
        g_xn[(size_t)warp * F_DIM + lane + 32 * t] = __float2bfloat16(v[t] * inv);
        g_neigh[(size_t)warp * F_DIM + lane + 32 * t] = 0.f;
    }
    if (lane == 0) g_deg[warp] = 0;
}

// ---------------- kernel 2: fused gram + threshold + sparse aggregation ----------------
// C = xn @ xn^T per 128x128 tile via mma.sync bf16.
// Only jb >= ib tiles computed (symmetry); edges update both directions.
__global__ void __launch_bounds__(256) k_gram(const float* __restrict__ x) {
    int ib = blockIdx.y, jb = blockIdx.x;
    if (jb < ib) return;

    extern __shared__ __nv_bfloat16 smem[];
    __nv_bfloat16 (*As)[SSTRIDE] = reinterpret_cast<__nv_bfloat16 (*)[SSTRIDE]>(smem);
    __nv_bfloat16 (*Bs)[SSTRIDE] = reinterpret_cast<__nv_bfloat16 (*)[SSTRIDE]>(smem + TILE * SSTRIDE);

    int tid = threadIdx.x;
    const uint4* gA = reinterpret_cast<const uint4*>(g_xn + (size_t)ib * TILE * F_DIM);
    const uint4* gB = reinterpret_cast<const uint4*>(g_xn + (size_t)jb * TILE * F_DIM);
    for (int idx = tid; idx < TILE * 16; idx += 256) {
        int r = idx >> 4, c = idx & 15;
        *reinterpret_cast<uint4*>(&As[r][c * 8]) = gA[r * 16 + c];
        *reinterpret_cast<uint4*>(&Bs[r][c * 8]) = gB[r * 16 + c];
    }
    __syncthreads();

    int wid = tid >> 5, lane = tid & 31;
    int m0 = (wid & 3) * 32;   // 4 warps along M (32 rows each)
    int n0 = (wid >> 2) * 64;  // 2 warps along N (64 cols each)

    float acc[2][8][4];
#pragma unroll
    for (int mi = 0; mi < 2; mi++)
#pragma unroll
        for (int nj = 0; nj < 8; nj++)
#pragma unroll
            for (int r = 0; r < 4; r++) acc[mi][nj][r] = 0.f;

    // ldmatrix x4 lane->address mapping: quadrants (rows+0,k0)(rows+8,k0)(rows+0,k8)(rows+8,k8)
    int q  = lane >> 3, L = lane & 7;
    int rq = (q & 1) * 8 + L;
    int kq = (q >> 1) * 8;

#pragma unroll
    for (int kk = 0; kk < F_DIM; kk += 16) {
        uint32_t a[2][4];
#pragma unroll
        for (int mi = 0; mi < 2; mi++) {
            uint32_t addr = (uint32_t)__cvta_generic_to_shared(&As[m0 + mi * 16 + rq][kk + kq]);
            asm volatile("ldmatrix.sync.aligned.m8n8.x4.shared.b16 {%0,%1,%2,%3}, [%4];"
                         : "=r"(a[mi][0]), "=r"(a[mi][1]), "=r"(a[mi][2]), "=r"(a[mi][3])
                         : "r"(addr));
        }
        uint32_t b[8][2];
#pragma unroll
        for (int nq4 = 0; nq4 < 4; nq4++) {
            uint32_t r0, r1, r2, r3;
            uint32_t addr = (uint32_t)__cvta_generic_to_shared(&Bs[n0 + nq4 * 16 + rq][kk + kq]);
            asm volatile("ldmatrix.sync.aligned.m8n8.x4.shared.b16 {%0,%1,%2,%3}, [%4];"
                         : "=r"(r0), "=r"(r1), "=r"(r2), "=r"(r3)
                         : "r"(addr));
            // quadrants: m0=(n..n+7,k0-7) m1=(n+8..,k0-7) m2=(n..,k8-15) m3=(n+8..,k8-15)
            b[nq4 * 2 + 0][0] = r0; b[nq4 * 2 + 0][1] = r2;
            b[nq4 * 2 + 1][0] = r1; b[nq4 * 2 + 1][1] = r3;
        }
#pragma unroll
        for (int mi = 0; mi < 2; mi++)
#pragma unroll
            for (int nj = 0; nj < 8; nj++)
                asm volatile(
                    "mma.sync.aligned.m16n8k16.row.col.f32.bf16.bf16.f32 "
                    "{%0,%1,%2,%3}, {%4,%5,%6,%7}, {%8,%9}, {%0,%1,%2,%3};"
                    : "+f"(acc[mi][nj][0]), "+f"(acc[mi][nj][1]),
                      "+f"(acc[mi][nj][2]), "+f"(acc[mi][nj][3])
                    : "r"(a[mi][0]), "r"(a[mi][1]), "r"(a[mi][2]), "r"(a[mi][3]),
                      "r"(b[nj][0]), "r"(b[nj][1]));
    }

    // epilogue: fid threshold + (rare) symmetric edge accumulation
    int g = lane >> 2, tg = lane & 3;
#pragma unroll
    for (int mi = 0; mi < 2; mi++) {
#pragma unroll
        for (int nj = 0; nj < 8; nj++) {
#pragma unroll
            for (int r = 0; r < 4; r++) {
                float c = acc[mi][nj][r];
                float fid = c * c;
                if (fid >= 0.9f) {
                    int i = ib * TILE + m0 + mi * 16 + g + (r >> 1) * 8;
                    int j = jb * TILE + n0 + nj * 8 + 2 * tg + (r & 1);
                    if (i < j) {  // off-diag tiles: always true; diag tile: upper half, excludes self
                        atomicAdd(&g_deg[i], 1);
                        atomicAdd(&g_deg[j], 1);
                        const float* xi = x + (size_t)i * F_DIM;
                        const float* xj = x + (size_t)j * F_DIM;
                        float* ni = g_neigh + (size_t)i * F_DIM;
                        float* nj_ = g_neigh + (size_t)j * F_DIM;
                        for (int f = 0; f < F_DIM; f++) {
                            atomicAdd(&ni[f], xj[f]);
                            atomicAdd(&nj_[f], xi[f]);
                        }
                    }
                }
            }
        }
    }
}

// ---------------- kernel 3: aggregation + MLP + BN statistics ----------------
__global__ void __launch_bounds__(256) k_mlp(const float* __restrict__ x,
                                             const float* __restrict__ W1, const float* __restrict__ b1,
                                             const float* __restrict__ W2, const float* __restrict__ b2,
                                             const float* __restrict__ W3, const float* __restrict__ b3) {
    __shared__ float sW1[F_DIM * H1_DIM];
    __shared__ float sW2[H1_DIM * H2_DIM];
    __shared__ float sW3[H2_DIM * OUT_DIM];
    __shared__ float sb1[H1_DIM], sb2[H2_DIM], sb3[OUT_DIM];
    __shared__ double swarp[8 * 4];

    int tid = threadIdx.x;
    for (int i = tid; i < F_DIM * H1_DIM; i += 256) sW1[i] = W1[i];
    for (int i = tid; i < H1_DIM * H2_DIM; i += 256) sW2[i] = W2[i];
    if (tid < H2_DIM * OUT_DIM) sW3[tid] = W3[tid];
    if (tid < H1_DIM) sb1[tid] = b1[tid];
    if (tid < H2_DIM) sb2[tid] = b2[tid];
    if (tid < OUT_DIM) sb3[tid] = b3[tid];
    __syncthreads();

    int row = blockIdx.x * 256 + tid;
    const float* xr = x + (size_t)row * F_DIM;
    const float* nr = g_neigh + (size_t)row * F_DIM;
    int d = g_deg[row];
    float invd = d > 0 ? 1.0f / (float)d : 0.f;

    float h1[H1_DIM];
#pragma unroll
    for (int k = 0; k < H1_DIM; k++) h1[k] = sb1[k];
    for (int f = 0; f < F_DIM; f++) {
        float a = (d > 0) ? 0.5f * (xr[f] + nr[f] * invd) : xr[f];
#pragma unroll
        for (int k = 0; k < H1_DIM; k++) h1[k] += a * sW1[f * H1_DIM + k];
    }
    float h2[H2_DIM];
#pragma unroll
    for (int m = 0; m < H2_DIM; m++) h2[m] = sb2[m];
#pragma unroll
    for (int k = 0; k < H1_DIM; k++) {
        float hk = fmaxf(h1[k], 0.f);
#pragma unroll
        for (int m = 0; m < H2_DIM; m++) h2[m] += hk * sW2[k * H2_DIM + m];
    }
    float l0 = sb3[0], l1 = sb3[1];
#pragma unroll
    for (int m = 0; m < H2_DIM; m++) {
        float hm = fmaxf(h2[m], 0.f);
        l0 += hm * sW3[m * 2 + 0];
        l1 += hm * sW3[m * 2 + 1];
    }
    g_logits[row * 2 + 0] = l0;
    g_logits[row * 2 + 1] = l1;

    // block-level BN statistics (double) -> 4 atomics per block
    double v[4] = { (double)l0, (double)l1, (double)l0 * l0, (double)l1 * l1 };
    int lane = tid & 31, wid = tid >> 5;
#pragma unroll
    for (int s = 0; s < 4; s++) {
        double t = v[s];
#pragma unroll
        for (int o = 16; o > 0; o >>= 1) t += __shfl_xor_sync(0xffffffffu, t, o);
        if (lane == 0) swarp[wid * 4 + s] = t;
    }
    __syncthreads();
    if (tid < 4) {
        double s = 0.0;
#pragma unroll
        for (int w = 0; w < 8; w++) s += swarp[w * 4 + tid];
        if (tid < 2) atomicAdd(&g_sum[tid], s);
        else         atomicAdd(&g_sq[tid - 2], s);
    }
}

// ---------------- kernel 4: batch-norm normalize ----------------
__global__ void __launch_bounds__(256) k_bn(const float* __restrict__ gamma,
                                            const float* __restrict__ beta,
                                            float* __restrict__ out) {
    int idx = blockIdx.x * blockDim.x + threadIdx.x;
    if (idx >= N_ROWS * OUT_DIM) return;
    int c = idx & 1;
    double n = (double)N_ROWS;
    double mu = g_sum[c] / n;
    double var = g_sq[c] / n - mu * mu;
    double inv = 1.0 / sqrt(var + 1e-5);
    out[idx] = (float)(((double)g_logits[idx] - mu) * inv) * gamma[c] + beta[c];
}

// ---------------- launch ----------------
extern "C" void kernel_launch(void* const* d_in, const int* in_sizes, int n_in,
                              void* d_out, int out_size) {
    const float* x     = (const float*)d_in[0];
    const float* W1    = (const float*)d_in[1];
    const float* b1    = (const float*)d_in[2];
    const float* W2    = (const float*)d_in[3];
    const float* b2    = (const float*)d_in[4];
    const float* W3    = (const float*)d_in[5];
    const float* b3    = (const float*)d_in[6];
    const float* gamma = (const float*)d_in[7];
    const float* beta  = (const float*)d_in[8];
    float* out = (float*)d_out;

    k_norm<<<(N_ROWS / 8 + 0), 256>>>(x);  // 2048 blocks * 8 warps = 16384 rows

    int smem_bytes = 2 * TILE * SSTRIDE * (int)sizeof(__nv_bfloat16);  // 69632
    cudaFuncSetAttribute(k_gram, cudaFuncAttributeMaxDynamicSharedMemorySize, smem_bytes);
    dim3 grid(TILE, TILE);  // (128, 128) tile pairs; lower triangle exits early
    k_gram<<<grid, 256, smem_bytes>>>(x);

    k_mlp<<<N_ROWS / 256, 256>>>(x, W1, b1, W2, b2, W3, b3);
    k_bn<<<(N_ROWS * OUT_DIM + 255) / 256, 256>>>(gamma, beta, out);
}

// round 3
// speedup vs baseline: 1.7217x; 1.7217x over previous
#include <cuda_runtime.h>
#include <cuda_bf16.h>
#include <cuda_fp8.h>
#include <cstdint>
#include <math.h>

#define N_ROWS 16384
#define F_DIM  128
#define H1_DIM 64
#define H2_DIM 32
#define OUT_DIM 2

#define TB      128                       // gram tile (square)
#define NB      (N_ROWS / TB)             // 128 tile-blocks
#define N_TILES (NB * (NB + 1) / 2)       // 8256

// ---------------- device scratch ----------------
__device__ uint32_t g_x8[N_ROWS * 32];     // 2 MB: rows of 128 e4m3 (32 u32)
__device__ float    g_neigh[N_ROWS * F_DIM];
__device__ int      g_deg[N_ROWS];
__device__ float    g_logits[N_ROWS * OUT_DIM];
__device__ double   g_sum[2];
__device__ double   g_sq[2];

__device__ __forceinline__ uint32_t smem_u32(const void* p) {
    uint32_t a;
    asm("{ .reg .u64 t; cvta.to.shared.u64 t, %1; cvt.u32.u64 %0, t; }" : "=r"(a) : "l"(p));
    return a;
}

// byte offset inside a [128 x 128B] tile with per-row XOR swizzle (16B lanes)
__device__ __forceinline__ uint32_t swz_off(int r, int c16) {
    return (uint32_t)(r * 128 + ((c16 ^ (r & 7)) << 4));
}

// ---------------- kernel 1: row norms -> e4m3, zero scratch ----------------
__global__ void __launch_bounds__(256) k_norm(const float* __restrict__ x) {
    if (blockIdx.x == 0 && threadIdx.x == 0) {
        g_sum[0] = 0.0; g_sum[1] = 0.0; g_sq[0] = 0.0; g_sq[1] = 0.0;
    }
    int warp = (blockIdx.x * blockDim.x + threadIdx.x) >> 5;
    int lane = threadIdx.x & 31;
    if (warp >= N_ROWS) return;
    float4 v = reinterpret_cast<const float4*>(x)[(size_t)warp * 32 + lane];
    float s = v.x * v.x + v.y * v.y + v.z * v.z + v.w * v.w;
#pragma unroll
    for (int o = 16; o > 0; o >>= 1) s += __shfl_xor_sync(0xffffffffu, s, o);
    float inv = 1.0f / (sqrtf(s) + 1e-12f);
    __nv_fp8x2_storage_t p0 = __nv_cvt_float2_to_fp8x2(make_float2(v.x * inv, v.y * inv),
                                                       __NV_SATFINITE, __NV_E4M3);
    __nv_fp8x2_storage_t p1 = __nv_cvt_float2_to_fp8x2(make_float2(v.z * inv, v.w * inv),
                                                       __NV_SATFINITE, __NV_E4M3);
    g_x8[warp * 32 + lane] = (uint32_t)p0 | ((uint32_t)p1 << 16);
    reinterpret_cast<float4*>(g_neigh)[(size_t)warp * 32 + lane] = make_float4(0.f, 0.f, 0.f, 0.f);
    if (lane == 0) g_deg[warp] = 0;
}

// ---------------- kernel 2: fp8 gram + threshold + sparse aggregation ----------------
__global__ void __launch_bounds__(256, 2) k_gram(const float* __restrict__ x) {
    // triangular decode (count from the last tile backwards)
    int u = N_TILES - 1 - blockIdx.x;
    int rb = (int)((sqrtf(8.0f * (float)u + 1.0f) - 1.0f) * 0.5f);
    while (rb * (rb + 1) / 2 > u) rb--;              // fixup for float rounding
    while ((rb + 1) * (rb + 2) / 2 <= u) rb++;
    int ib = NB - 1 - rb;
    int jb = NB - 1 - (u - rb * (rb + 1) / 2);
    bool diag = (ib == jb);

    __shared__ char sA[TB * 128];
    __shared__ char sB[TB * 128];

    int tid = threadIdx.x;
    uint32_t sa = smem_u32(sA), sbm = smem_u32(sB);

    // async-load tiles: 1024 x 16B each; thread handles 4 chunks per tile
    const char* gA = reinterpret_cast<const char*>(g_x8 + (size_t)ib * TB * 32);
    const char* gB = reinterpret_cast<const char*>(g_x8 + (size_t)jb * TB * 32);
#pragma unroll
    for (int it = 0; it < 4; it++) {
        int idx = tid + it * 256;
        int r = idx >> 3, c16 = idx & 7;
        uint32_t so = swz_off(r, c16);
        asm volatile("cp.async.cg.shared.global [%0], [%1], 16;"
                     :: "r"(sa + so), "l"(gA + idx * 16));
        if (!diag)
            asm volatile("cp.async.cg.shared.global [%0], [%1], 16;"
                         :: "r"(sbm + so), "l"(gB + idx * 16));
    }
    asm volatile("cp.async.commit_group;");
    asm volatile("cp.async.wait_group 0;");
    __syncthreads();

    uint32_t sb_use = diag ? sa : sbm;

    int wid = tid >> 5, lane = tid & 31;
    int m0 = (wid & 3) * 32;   // 4 warps along M
    int n0 = (wid >> 2) * 64;  // 2 warps along N

    float acc[2][8][4];
#pragma unroll
    for (int mi = 0; mi < 2; mi++)
#pragma unroll
        for (int nj = 0; nj < 8; nj++)
#pragma unroll
            for (int r = 0; r < 4; r++) acc[mi][nj][r] = 0.f;

    // ldmatrix lane->addr: quadrant q, row rq, 16B-col kq
    int q = lane >> 3, L = lane & 7;
    int rq = (q & 1) * 8 + L;
    int kq = q >> 1;

#pragma unroll
    for (int kk = 0; kk < 4; kk++) {           // 4 chunks of k=32 fp8 (2 x 16B)
        int cbase = kk * 2 + kq;
        uint32_t a[2][4];
#pragma unroll
        for (int mi = 0; mi < 2; mi++) {
            uint32_t addr = sa + swz_off(m0 + mi * 16 + rq, cbase);
            asm volatile("ldmatrix.sync.aligned.m8n8.x4.shared.b16 {%0,%1,%2,%3}, [%4];"
                         : "=r"(a[mi][0]), "=r"(a[mi][1]), "=r"(a[mi][2]), "=r"(a[mi][3])
                         : "r"(addr));
        }
        uint32_t b[8][2];
#pragma unroll
        for (int nq4 = 0; nq4 < 4; nq4++) {
            uint32_t r0, r1, r2, r3;
            uint32_t addr = sb_use + swz_off(n0 + nq4 * 16 + rq, cbase);
            asm volatile("ldmatrix.sync.aligned.m8n8.x4.shared.b16 {%0,%1,%2,%3}, [%4];"
                         : "=r"(r0), "=r"(r1), "=r"(r2), "=r"(r3)
                         : "r"(addr));
            b[nq4 * 2 + 0][0] = r0; b[nq4 * 2 + 0][1] = r2;
            b[nq4 * 2 + 1][0] = r1; b[nq4 * 2 + 1][1] = r3;
        }
#pragma unroll
        for (int mi = 0; mi < 2; mi++)
#pragma unroll
            for (int nj = 0; nj < 8; nj++)
                asm volatile(
                    "mma.sync.aligned.m16n8k32.row.col.f32.e4m3.e4m3.f32 "
                    "{%0,%1,%2,%3}, {%4,%5,%6,%7}, {%8,%9}, {%0,%1,%2,%3};"
                    : "+f"(acc[mi][nj][0]), "+f"(acc[mi][nj][1]),
                      "+f"(acc[mi][nj][2]), "+f"(acc[mi][nj][3])
                    : "r"(a[mi][0]), "r"(a[mi][1]), "r"(a[mi][2]), "r"(a[mi][3]),
                      "r"(b[nj][0]), "r"(b[nj][1]));
    }

    // epilogue: screened threshold + (rare) symmetric edge accumulation
    int g = lane >> 2, tg = lane & 3;
#pragma unroll
    for (int mi = 0; mi < 2; mi++) {
#pragma unroll
        for (int nj = 0; nj < 8; nj++) {
            float c0 = acc[mi][nj][0], c1 = acc[mi][nj][1];
            float c2 = acc[mi][nj][2], c3 = acc[mi][nj][3];
            float m = fmaxf(fmaxf(fabsf(c0), fabsf(c1)), fmaxf(fabsf(c2), fabsf(c3)));
            if (__any_sync(0xffffffffu, m >= 0.9486f)) {
#pragma unroll
                for (int r = 0; r < 4; r++) {
                    float c = acc[mi][nj][r];
                    if (c * c >= 0.9f) {
                        int i = ib * TB + m0 + mi * 16 + g + (r >> 1) * 8;
                        int j = jb * TB + n0 + nj * 8 + 2 * tg + (r & 1);
                        if (i < j) {
                            atomicAdd(&g_deg[i], 1);
                            atomicAdd(&g_deg[j], 1);
                            const float* xi = x + (size_t)i * F_DIM;
                            const float* xj = x + (size_t)j * F_DIM;
                            float* ni = g_neigh + (size_t)i * F_DIM;
                            float* nj_ = g_neigh + (size_t)j * F_DIM;
                            for (int f = 0; f < F_DIM; f++) {
                                atomicAdd(&ni[f], xj[f]);
                                atomicAdd(&nj_[f], xi[f]);
                            }
                        }
                    }
                }
            }
        }
    }
}

// ---------------- kernel 3: aggregation + MLP + BN statistics ----------------
__global__ void __launch_bounds__(256) k_mlp(const float* __restrict__ x,
                                             const float* __restrict__ W1, const float* __restrict__ b1,
                                             const float* __restrict__ W2, const float* __restrict__ b2,
                                             const float* __restrict__ W3, const float* __restrict__ b3) {
    __shared__ float sW1[F_DIM * H1_DIM];
    __shared__ float sW2[H1_DIM * H2_DIM];
    __shared__ float sW3[H2_DIM * OUT_DIM];
    __shared__ float sb1[H1_DIM], sb2[H2_DIM], sb3[OUT_DIM];
    __shared__ double swarp[8 * 4];

    int tid = threadIdx.x;
    for (int i = tid; i < F_DIM * H1_DIM; i += 256) sW1[i] = W1[i];
    for (int i = tid; i < H1_DIM * H2_DIM; i += 256) sW2[i] = W2[i];
    if (tid < H2_DIM * OUT_DIM) sW3[tid] = W3[tid];
    if (tid < H1_DIM) sb1[tid] = b1[tid];
    if (tid < H2_DIM) sb2[tid] = b2[tid];
    if (tid < OUT_DIM) sb3[tid] = b3[tid];
    __syncthreads();

    int row = blockIdx.x * 256 + tid;
    const float* xr = x + (size_t)row * F_DIM;
    const float* nr = g_neigh + (size_t)row * F_DIM;
    int d = g_deg[row];
    float invd = d > 0 ? 1.0f / (float)d : 0.f;

    float h1[H1_DIM];
#pragma unroll
    for (int k = 0; k < H1_DIM; k++) h1[k] = sb1[k];
    for (int f = 0; f < F_DIM; f++) {
        float a = (d > 0) ? 0.5f * (xr[f] + nr[f] * invd) : xr[f];
#pragma unroll
        for (int k = 0; k < H1_DIM; k++) h1[k] += a * sW1[f * H1_DIM + k];
    }
    float h2[H2_DIM];
#pragma unroll
    for (int m = 0; m < H2_DIM; m++) h2[m] = sb2[m];
#pragma unroll
    for (int k = 0; k < H1_DIM; k++) {
        float hk = fmaxf(h1[k], 0.f);
#pragma unroll
        for (int m = 0; m < H2_DIM; m++) h2[m] += hk * sW2[k * H2_DIM + m];
    }
    float l0 = sb3[0], l1 = sb3[1];
#pragma unroll
    for (int m = 0; m < H2_DIM; m++) {
        float hm = fmaxf(h2[m], 0.f);
        l0 += hm * sW3[m * 2 + 0];
        l1 += hm * sW3[m * 2 + 1];
    }
    g_logits[row * 2 + 0] = l0;
    g_logits[row * 2 + 1] = l1;

    double v[4] = { (double)l0, (double)l1, (double)l0 * l0, (double)l1 * l1 };
    int lane = tid & 31, wid = tid >> 5;
#pragma unroll
    for (int s = 0; s < 4; s++) {
        double t = v[s];
#pragma unroll
        for (int o = 16; o > 0; o >>= 1) t += __shfl_xor_sync(0xffffffffu, t, o);
        if (lane == 0) swarp[wid * 4 + s] = t;
    }
    __syncthreads();
    if (tid < 4) {
        double s = 0.0;
#pragma unroll
        for (int w = 0; w < 8; w++) s += swarp[w * 4 + tid];
        if (tid < 2) atomicAdd(&g_sum[tid], s);
        else         atomicAdd(&g_sq[tid - 2], s);
    }
}

// ---------------- kernel 4: batch-norm normalize ----------------
__global__ void __launch_bounds__(256) k_bn(const float* __restrict__ gamma,
                                            const float* __restrict__ beta,
                                            float* __restrict__ out) {
    __shared__ float s_scale[2], s_shift[2];
    if (threadIdx.x < 2) {
        int c = threadIdx.x;
        double n = (double)N_ROWS;
        double mu = g_sum[c] / n;
        double var = g_sq[c] / n - mu * mu;
        double inv = 1.0 / sqrt(var + 1e-5);
        float g = gamma[c];
        s_scale[c] = (float)inv * g;
        s_shift[c] = beta[c] - (float)(mu * inv) * g;
    }
    __syncthreads();
    int idx = blockIdx.x * blockDim.x + threadIdx.x;
    if (idx >= N_ROWS * OUT_DIM) return;
    int c = idx & 1;
    out[idx] = g_logits[idx] * s_scale[c] + s_shift[c];
}

// ---------------- launch ----------------
extern "C" void kernel_launch(void* const* d_in, const int* in_sizes, int n_in,
                              void* d_out, int out_size) {
    const float* x     = (const float*)d_in[0];
    const float* W1    = (const float*)d_in[1];
    const float* b1    = (const float*)d_in[2];
    const float* W2    = (const float*)d_in[3];
    const float* b2    = (const float*)d_in[4];
    const float* W3    = (const float*)d_in[5];
    const float* b3    = (const float*)d_in[6];
    const float* gamma = (const float*)d_in[7];
    const float* beta  = (const float*)d_in[8];
    float* out = (float*)d_out;

    k_norm<<<N_ROWS / 8, 256>>>(x);
    k_gram<<<N_TILES, 256>>>(x);
    k_mlp<<<N_ROWS / 256, 256>>>(x, W1, b1, W2, b2, W3, b3);
    k_bn<<<(N_ROWS * OUT_DIM + 255) / 256, 256>>>(gamma, beta, out);
}